// round 16
// baseline (speedup 1.0000x reference)
#include <cuda_runtime.h>
#include <cuda_fp16.h>
#include <math.h>
#include <stdint.h>

#define Bn   4
#define Mn   2048
#define Cn   1024
#define Hn   8
#define DQK  32
#define DV   128
#define ROWS (Bn*Mn)
#define QSCALE 0.25503695218998236f  // (1/sqrt(32))*log2(e)
#define NSM   148

__device__ __half g_Xh[ROWS * Cn];
__device__ __half g_Yh[ROWS * Cn];
__device__ __half g_Wqh[Cn * 256];
__device__ __half g_Wkh[Cn * 256];
__device__ __half g_Wvh[Cn * Cn];
__device__ __half g_Q[ROWS * 256];
__device__ __half g_K[ROWS * 256];
__device__ __half g_V[ROWS * 1024];

// ---------------- helpers ----------------
__device__ __forceinline__ uint32_t smem_u32(const void* p) {
    return (uint32_t)__cvta_generic_to_shared(p);
}
__device__ __forceinline__ uint32_t pack_f16(float lo, float hi) {
    uint32_t r;
    asm("cvt.rn.f16x2.f32 %0, %1, %2;" : "=r"(r) : "f"(hi), "f"(lo));
    return r;
}
// leaky-relu (slope 0.2) + exp2 on two packed values; result = f16x2 P fragment
__device__ __forceinline__ uint32_t exp2_pair(float v0, float v1) {
    uint32_t hv = pack_f16(v0, v1), hs, he;
    asm("mul.f16x2 %0, %1, %2;" : "=r"(hs) : "r"(hv), "r"(0x32663266u));  // *0.2
    asm("max.f16x2 %0, %1, %2;" : "=r"(hv) : "r"(hv), "r"(hs));           // leaky
    asm("ex2.approx.f16x2 %0, %1;" : "=r"(he) : "r"(hv));                 // 1 MUFU / 2 vals
    return he;
}
__device__ __forceinline__ void ldsm_x4(uint32_t a, uint32_t& r0, uint32_t& r1,
                                        uint32_t& r2, uint32_t& r3) {
    asm volatile("ldmatrix.sync.aligned.m8n8.x4.shared.b16 {%0,%1,%2,%3}, [%4];"
                 : "=r"(r0), "=r"(r1), "=r"(r2), "=r"(r3) : "r"(a));
}
__device__ __forceinline__ void ldsm_x4_t(uint32_t a, uint32_t& r0, uint32_t& r1,
                                          uint32_t& r2, uint32_t& r3) {
    asm volatile("ldmatrix.sync.aligned.m8n8.x4.trans.shared.b16 {%0,%1,%2,%3}, [%4];"
                 : "=r"(r0), "=r"(r1), "=r"(r2), "=r"(r3) : "r"(a));
}
__device__ __forceinline__ void mma16816h(float* c, const uint32_t* a, uint32_t b0, uint32_t b1) {
    asm volatile(
        "mma.sync.aligned.m16n8k16.row.col.f32.f16.f16.f32 "
        "{%0,%1,%2,%3}, {%4,%5,%6,%7}, {%8,%9}, {%0,%1,%2,%3};"
        : "+f"(c[0]), "+f"(c[1]), "+f"(c[2]), "+f"(c[3])
        : "r"(a[0]), "r"(a[1]), "r"(a[2]), "r"(a[3]), "r"(b0), "r"(b1));
}
__device__ __forceinline__ void cp16(void* dst, const void* src) {
    asm volatile("cp.async.cg.shared.global [%0], [%1], 16;"
                 :: "r"(smem_u32(dst)), "l"(src) : "memory");
}
__device__ __forceinline__ void cp_commit() {
    asm volatile("cp.async.commit_group;" ::: "memory");
}
template <int N>
__device__ __forceinline__ void cp_wait() {
    asm volatile("cp.async.wait_group %0;" :: "n"(N) : "memory");
}

// ---------------- fp32 -> f16 convert (4 float4 per thread) ----------------
__global__ void __launch_bounds__(256) cvt_all(
    const float* __restrict__ x, const float* __restrict__ y,
    const float* __restrict__ wq, const float* __restrict__ wk,
    const float* __restrict__ wv)
{
    int bid = blockIdx.x;
    const float* src;
    __half* dst;
    int base;
    if (bid < 2048)      { src = x;  dst = g_Xh;  base = bid; }
    else if (bid < 4096) { src = y;  dst = g_Yh;  base = bid - 2048; }
    else if (bid < 4160) { src = wq; dst = g_Wqh; base = bid - 4096; }
    else if (bid < 4224) { src = wk; dst = g_Wkh; base = bid - 4160; }
    else                 { src = wv; dst = g_Wvh; base = bid - 4224; }
    #pragma unroll
    for (int i = 0; i < 4; i++) {
        size_t off = (size_t)base * 4096 + i * 1024 + threadIdx.x * 4;
        float4 f = *(const float4*)(src + off);
        uint2 u;
        u.x = pack_f16(f.x, f.y);
        u.y = pack_f16(f.z, f.w);
        *(uint2*)(dst + off) = u;
    }
}

// ---------------- persistent fused projection GEMM: 2-stage, 256 thr ----------------
__global__ void __launch_bounds__(256, 2) gemm_fused(
    const float* __restrict__ bq, const float* __restrict__ bk,
    const float* __restrict__ bv)
{
    extern __shared__ char smem[];
    auto Ast = [&](int s) { return (__half(*)[72])(smem + s * 35840); };
    auto Wst = [&](int s) { return (__half(*)[136])(smem + s * 35840 + 18432); };

    const int tid  = threadIdx.x;
    const int lane = tid & 31;
    const int warp = tid >> 5;
    const int wm   = warp >> 1;
    const int wn   = warp & 1;

    for (int item = blockIdx.x; item < 768; item += gridDim.x) {
        int bid = item;
        const __half *A, *W;
        const float* bias;
        __half* out;
        int N, bx, by;
        float oscale;
        if (bid < 128)      { A = g_Xh; W = g_Wqh; bias = bq; out = g_Q; N = 256;
                              bx = bid & 1;  by = bid >> 1; oscale = QSCALE; }
        else if (bid < 256) { bid -= 128; A = g_Yh; W = g_Wkh; bias = bk; out = g_K; N = 256;
                              bx = bid & 1;  by = bid >> 1; oscale = 1.f; }
        else                { bid -= 256; A = g_Yh; W = g_Wvh; bias = bv; out = g_V; N = 1024;
                              bx = bid & 7;  by = bid >> 3; oscale = 1.f; }
        const int m0 = by * 128;
        const int n0 = bx * 128;

        auto loadTile = [&](int s, int it) {
            __half (*Ad)[72]  = Ast(s);
            __half (*Wd)[136] = Wst(s);
            #pragma unroll
            for (int i = 0; i < 4; i++) {
                int idx = tid + i * 256;
                int r = idx >> 3, c = idx & 7;
                cp16(&Ad[r][c * 8], A + (size_t)(m0 + r) * 1024 + it * 64 + c * 8);
            }
            #pragma unroll
            for (int i = 0; i < 4; i++) {
                int idx = tid + i * 256;
                int r = idx >> 4, c = idx & 15;
                cp16(&Wd[r][c * 8], W + (size_t)(it * 64 + r) * N + n0 + c * 8);
            }
            cp_commit();
        };

        float acc[2][8][4] = {};
        loadTile(0, 0);

        for (int it = 0; it < 16; it++) {
            if (it < 15) {
                loadTile((it + 1) & 1, it + 1);
                cp_wait<1>();
            } else {
                cp_wait<0>();
            }
            __syncthreads();

            __half (*Ab)[72]  = Ast(it & 1);
            __half (*Wb)[136] = Wst(it & 1);
            #pragma unroll
            for (int ks = 0; ks < 4; ks++) {
                uint32_t afr[2][4];
                #pragma unroll
                for (int mt = 0; mt < 2; mt++) {
                    int row = wm * 32 + mt * 16 + ((lane >> 3) & 1) * 8 + (lane & 7);
                    int col = ks * 16 + (lane >> 4) * 8;
                    ldsm_x4(smem_u32(&Ab[row][col]), afr[mt][0], afr[mt][1], afr[mt][2], afr[mt][3]);
                }
                #pragma unroll
                for (int np = 0; np < 4; np++) {
                    int rowb = ks * 16 + (lane & 15);
                    int colb = wn * 64 + np * 16 + (lane >> 4) * 8;
                    uint32_t b0, b1, b2, b3;
                    ldsm_x4_t(smem_u32(&Wb[rowb][colb]), b0, b1, b2, b3);
                    #pragma unroll
                    for (int mt = 0; mt < 2; mt++) {
                        mma16816h(acc[mt][np * 2 + 0], afr[mt], b0, b1);
                        mma16816h(acc[mt][np * 2 + 1], afr[mt], b2, b3);
                    }
                }
            }
            __syncthreads();
        }

        const int g = lane >> 2, q = lane & 3;
        #pragma unroll
        for (int mt = 0; mt < 2; mt++) {
            #pragma unroll
            for (int nt = 0; nt < 8; nt++) {
                int r = m0 + wm * 32 + mt * 16 + g;
                int c = n0 + wn * 64 + nt * 8 + q * 2;
                float b0 = __ldg(bias + c), b1 = __ldg(bias + c + 1);
                *(uint32_t*)(out + (size_t)r * N + c) =
                    pack_f16((acc[mt][nt][0] + b0) * oscale, (acc[mt][nt][1] + b1) * oscale);
                *(uint32_t*)(out + (size_t)(r + 8) * N + c) =
                    pack_f16((acc[mt][nt][2] + b0) * oscale, (acc[mt][nt][3] + b1) * oscale);
            }
        }
        __syncthreads();   // epilogue regs flushed; next item may rewrite stage smem
    }
}

// ---------------- persistent flash attention, dv-split, f16x2 softmax ----------------
// 1024 work items over 296 CTAs. smem: Q[128][40] @0 | K 3x[128][40] @10240 |
// V 3x[128][88] @40960 (col 64 = ones)  -> 108,544 B, 2 CTAs/SM
__global__ void __launch_bounds__(256, 2) attn_kernel(
    const float* __restrict__ x, const float* __restrict__ gamma,
    float* __restrict__ out)
{
    extern __shared__ char smem[];
    __half (*Qs)[40] = (__half(*)[40])(smem);
    const int tid  = threadIdx.x;
    const int lane = tid & 31;
    const int warp = tid >> 5;

    auto Kst = [&](int s) { return (__half(*)[40])(smem + 10240 + s * 10240); };
    auto Vst = [&](int s) { return (__half(*)[88])(smem + 40960 + s * 22528); };

    // ones-columns: written once; loadKV only touches V cols 0-63
    for (int i = tid; i < 3 * 128; i += 256) {
        int s = i >> 7, r = i & 127;
        __half* vr = &Vst(s)[r][0];
        vr[64] = __float2half(1.f);
        #pragma unroll
        for (int c = 65; c < 80; c++) vr[c] = __float2half(0.f);
    }
    __syncthreads();

    for (int item = blockIdx.x; item < 1024; item += gridDim.x) {
        const int qt = item & 15;
        const int hh = (item >> 4) & 15;
        const int b  = item >> 8;
        const int h = hh >> 1, dvh = hh & 1;

        const __half* Qg = g_Q + ((size_t)(b * Mn + qt * 128)) * 256 + h * DQK;
        const __half* Kg = g_K + ((size_t)(b * Mn)) * 256 + h * DQK;
        const __half* Vg = g_V + ((size_t)(b * Mn)) * 1024 + h * DV + dvh * 64;

        auto loadKV = [&](int s, int kt) {
            __half (*Ks)[40] = Kst(s);
            __half (*Vs)[88] = Vst(s);
            #pragma unroll
            for (int i = 0; i < 2; i++) {
                int idx = tid + i * 256;
                int r = idx >> 2, c = idx & 3;
                cp16(&Ks[r][c * 8], Kg + (size_t)(kt * 128 + r) * 256 + c * 8);
            }
            #pragma unroll
            for (int i = 0; i < 4; i++) {
                int idx = tid + i * 256;
                int r = idx >> 3, c = idx & 7;
                cp16(&Vs[r][c * 8], Vg + (size_t)(kt * 128 + r) * 1024 + c * 8);
            }
            cp_commit();
        };

        // Q tile [128][32]
        #pragma unroll
        for (int i = 0; i < 2; i++) {
            int idx = tid + i * 256;
            int r = idx >> 2, c = idx & 3;
            *(int4*)(&Qs[r][c * 8]) = *(const int4*)(Qg + (size_t)r * 256 + c * 8);
        }
        loadKV(0, 0);
        loadKV(1, 1);
        __syncthreads();

        uint32_t qfr[2][4];
        const int qrow0 = warp * 16;
        #pragma unroll
        for (int kc = 0; kc < 2; kc++) {
            int row = qrow0 + ((lane >> 3) & 1) * 8 + (lane & 7);
            int col = kc * 16 + (lane >> 4) * 8;
            ldsm_x4(smem_u32(&Qs[row][col]), qfr[kc][0], qfr[kc][1], qfr[kc][2], qfr[kc][3]);
        }

        float oacc[9][4];   // [0..7]: 64 dv cols; [8]: l (ones column)
        #pragma unroll
        for (int i = 0; i < 9; i++)
            #pragma unroll
            for (int j = 0; j < 4; j++) oacc[i][j] = 0.f;

        for (int kt = 0; kt < 16; kt++) {
            if (kt < 15) cp_wait<1>(); else cp_wait<0>();
            __syncthreads();
            __half (*Ks)[40] = Kst(kt % 3);
            __half (*Vs)[88] = Vst(kt % 3);

            uint32_t pfr[32];
            #pragma unroll
            for (int nt = 0; nt < 16; nt++) {
                float scv[4] = {0.f, 0.f, 0.f, 0.f};
                int rowb = nt * 8 + (lane & 7);
                int colb = (lane >> 3) * 8;
                uint32_t k0, k1, k2, k3;
                ldsm_x4(smem_u32(&Ks[rowb][colb]), k0, k1, k2, k3);
                mma16816h(scv, qfr[0], k0, k1);
                mma16816h(scv, qfr[1], k2, k3);
                pfr[2 * nt]     = exp2_pair(scv[0], scv[1]);
                pfr[2 * nt + 1] = exp2_pair(scv[2], scv[3]);
            }

            #pragma unroll
            for (int kc = 0; kc < 8; kc++) {
                uint32_t pa[4] = {pfr[4 * kc], pfr[4 * kc + 1], pfr[4 * kc + 2], pfr[4 * kc + 3]};
                int rowb = kc * 16 + (lane & 15);
                #pragma unroll
                for (int dp = 0; dp < 4; dp++) {
                    int colb = dp * 16 + (lane >> 4) * 8;
                    uint32_t v0, v1, v2, v3;
                    ldsm_x4_t(smem_u32(&Vs[rowb][colb]), v0, v1, v2, v3);
                    mma16816h(oacc[dp * 2 + 0], pa, v0, v1);
                    mma16816h(oacc[dp * 2 + 1], pa, v2, v3);
                }
                {   // l column
                    int colb = 64 + (lane >> 4) * 8;
                    uint32_t v0, v1, v2, v3;
                    ldsm_x4_t(smem_u32(&Vs[rowb][colb]), v0, v1, v2, v3);
                    mma16816h(oacc[8], pa, v0, v1);
                }
            }
            if (kt + 2 < 16) loadKV((kt + 2) % 3, kt + 2);
        }

        const float l0 = __shfl_sync(0xffffffffu, oacc[8][0], lane & 28);
        const float l1 = __shfl_sync(0xffffffffu, oacc[8][2], lane & 28);

        const float gm = gamma[0];
        const float il0 = gm / l0, il1 = gm / l1;
        const int g = lane >> 2, q = lane & 3;
        const size_t row0 = (size_t)b * Mn + qt * 128 + qrow0 + g;
        const size_t row1 = row0 + 8;
        #pragma unroll
        for (int d = 0; d < 8; d++) {
            int col = h * DV + dvh * 64 + d * 8 + q * 2;
            float2 x0 = *(const float2*)(x + row0 * Cn + col);
            float2 x1 = *(const float2*)(x + row1 * Cn + col);
            float2 r0, r1;
            r0.x = oacc[d][0] * il0 + x0.x;
            r0.y = oacc[d][1] * il0 + x0.y;
            r1.x = oacc[d][2] * il1 + x1.x;
            r1.y = oacc[d][3] * il1 + x1.y;
            *(float2*)(out + row0 * Cn + col) = r0;
            *(float2*)(out + row1 * Cn + col) = r1;
        }
        __syncthreads();   // stage-0 smem read at kt=15; next item rewrites it
    }
}

// ---------------- launch ----------------
extern "C" void kernel_launch(void* const* d_in, const int* in_sizes, int n_in,
                              void* d_out, int out_size)
{
    const float* x     = (const float*)d_in[0];
    const float* y     = (const float*)d_in[1];
    const float* Wq    = (const float*)d_in[2];
    const float* bq    = (const float*)d_in[3];
    const float* Wk    = (const float*)d_in[4];
    const float* bk    = (const float*)d_in[5];
    const float* Wv    = (const float*)d_in[6];
    const float* bv    = (const float*)d_in[7];
    const float* gamma = (const float*)d_in[8];
    float* out = (float*)d_out;

    cvt_all<<<4480, 256>>>(x, y, Wq, Wk, Wv);

    const int gemm_smem = 2 * 35840;   // 71,680 -> 2 CTAs/SM
    cudaFuncSetAttribute(gemm_fused, cudaFuncAttributeMaxDynamicSharedMemorySize, gemm_smem);
    gemm_fused<<<2 * NSM, 256, gemm_smem>>>(bq, bk, bv);

    const int attn_smem = 40960 + 3 * 22528;  // 108,544 -> 2 CTAs/SM
    cudaFuncSetAttribute(attn_kernel, cudaFuncAttributeMaxDynamicSharedMemorySize, attn_smem);
    attn_kernel<<<2 * NSM, 256, attn_smem>>>(x, gamma, out);
}

// round 17
// speedup vs baseline: 1.0438x; 1.0438x over previous
#include <cuda_runtime.h>
#include <cuda_fp16.h>
#include <math.h>
#include <stdint.h>

#define Bn   4
#define Mn   2048
#define Cn   1024
#define Hn   8
#define DQK  32
#define DV   128
#define ROWS (Bn*Mn)
#define QSCALE 0.25503695218998236f  // (1/sqrt(32))*log2(e)

__device__ __half g_Xh[ROWS * Cn];
__device__ __half g_Yh[ROWS * Cn];
__device__ __half g_Wqh[Cn * 256];
__device__ __half g_Wkh[Cn * 256];
__device__ __half g_Wvh[Cn * Cn];
__device__ __half g_Q[ROWS * 256];
__device__ __half g_K[ROWS * 256];
__device__ __half g_V[ROWS * 1024];

// ---------------- helpers ----------------
__device__ __forceinline__ uint32_t smem_u32(const void* p) {
    return (uint32_t)__cvta_generic_to_shared(p);
}
__device__ __forceinline__ uint32_t pack_f16(float lo, float hi) {
    uint32_t r;
    asm("cvt.rn.f16x2.f32 %0, %1, %2;" : "=r"(r) : "f"(hi), "f"(lo));
    return r;
}
// leaky-relu (slope 0.2) + exp2 on two packed values; result = f16x2 P fragment
__device__ __forceinline__ uint32_t exp2_pair(float v0, float v1) {
    uint32_t hv = pack_f16(v0, v1), hs, he;
    asm("mul.f16x2 %0, %1, %2;" : "=r"(hs) : "r"(hv), "r"(0x32663266u));  // *0.2
    asm("max.f16x2 %0, %1, %2;" : "=r"(hv) : "r"(hv), "r"(hs));           // leaky
    asm("ex2.approx.f16x2 %0, %1;" : "=r"(he) : "r"(hv));                 // 1 MUFU / 2 vals
    return he;
}
__device__ __forceinline__ void ldsm_x4(uint32_t a, uint32_t& r0, uint32_t& r1,
                                        uint32_t& r2, uint32_t& r3) {
    asm volatile("ldmatrix.sync.aligned.m8n8.x4.shared.b16 {%0,%1,%2,%3}, [%4];"
                 : "=r"(r0), "=r"(r1), "=r"(r2), "=r"(r3) : "r"(a));
}
__device__ __forceinline__ void ldsm_x4_t(uint32_t a, uint32_t& r0, uint32_t& r1,
                                          uint32_t& r2, uint32_t& r3) {
    asm volatile("ldmatrix.sync.aligned.m8n8.x4.trans.shared.b16 {%0,%1,%2,%3}, [%4];"
                 : "=r"(r0), "=r"(r1), "=r"(r2), "=r"(r3) : "r"(a));
}
__device__ __forceinline__ void mma16816h(float* c, const uint32_t* a, uint32_t b0, uint32_t b1) {
    asm volatile(
        "mma.sync.aligned.m16n8k16.row.col.f32.f16.f16.f32 "
        "{%0,%1,%2,%3}, {%4,%5,%6,%7}, {%8,%9}, {%0,%1,%2,%3};"
        : "+f"(c[0]), "+f"(c[1]), "+f"(c[2]), "+f"(c[3])
        : "r"(a[0]), "r"(a[1]), "r"(a[2]), "r"(a[3]), "r"(b0), "r"(b1));
}
__device__ __forceinline__ void cp16(void* dst, const void* src) {
    asm volatile("cp.async.cg.shared.global [%0], [%1], 16;"
                 :: "r"(smem_u32(dst)), "l"(src) : "memory");
}
__device__ __forceinline__ void cp_commit() {
    asm volatile("cp.async.commit_group;" ::: "memory");
}
template <int N>
__device__ __forceinline__ void cp_wait() {
    asm volatile("cp.async.wait_group %0;" :: "n"(N) : "memory");
}

// ---------------- fp32 -> f16 convert (4 float4 per thread) ----------------
__global__ void __launch_bounds__(256) cvt_all(
    const float* __restrict__ x, const float* __restrict__ y,
    const float* __restrict__ wq, const float* __restrict__ wk,
    const float* __restrict__ wv)
{
    int bid = blockIdx.x;
    const float* src;
    __half* dst;
    int base;
    if (bid < 2048)      { src = x;  dst = g_Xh;  base = bid; }
    else if (bid < 4096) { src = y;  dst = g_Yh;  base = bid - 2048; }
    else if (bid < 4160) { src = wq; dst = g_Wqh; base = bid - 4096; }
    else if (bid < 4224) { src = wk; dst = g_Wkh; base = bid - 4160; }
    else                 { src = wv; dst = g_Wvh; base = bid - 4224; }
    #pragma unroll
    for (int i = 0; i < 4; i++) {
        size_t off = (size_t)base * 4096 + i * 1024 + threadIdx.x * 4;
        float4 f = *(const float4*)(src + off);
        uint2 u;
        u.x = pack_f16(f.x, f.y);
        u.y = pack_f16(f.z, f.w);
        *(uint2*)(dst + off) = u;
    }
}

// ---------------- fused projection GEMM: 3-stage swizzled, 1 sync/iter, 2 CTAs/SM ----------------
// Stage: A 128x64h swizzled 128B rows (16 KB) + W 64x128h swizzled 256B rows (16 KB) = 32 KB.
// 3 stages = 96 KB -> 2 CTAs/SM. One __syncthreads per BK-iter (R12 pipeline shape).
__global__ void __launch_bounds__(256, 2) gemm_fused(
    const float* __restrict__ bq, const float* __restrict__ bk,
    const float* __restrict__ bv)
{
    extern __shared__ char smem[];
    auto Ast = [&](int s) { return smem + s * 32768; };
    auto Wst = [&](int s) { return smem + s * 32768 + 16384; };

    const int tid  = threadIdx.x;
    const int lane = tid & 31;
    const int warp = tid >> 5;
    const int wm   = warp >> 1;
    const int wn   = warp & 1;

    int bid = blockIdx.x;
    const __half *A, *W;
    const float* bias;
    __half* out;
    int N, bx, by;
    float oscale;
    if (bid < 128)      { A = g_Xh; W = g_Wqh; bias = bq; out = g_Q; N = 256;
                          bx = bid & 1;  by = bid >> 1; oscale = QSCALE; }
    else if (bid < 256) { bid -= 128; A = g_Yh; W = g_Wkh; bias = bk; out = g_K; N = 256;
                          bx = bid & 1;  by = bid >> 1; oscale = 1.f; }
    else                { bid -= 256; A = g_Yh; W = g_Wvh; bias = bv; out = g_V; N = 1024;
                          bx = bid & 7;  by = bid >> 3; oscale = 1.f; }
    const int m0 = by * 128;
    const int n0 = bx * 128;

    auto loadTile = [&](int s, int it) {
        char* Ad = Ast(s);
        char* Wd = Wst(s);
        // A tile: 128 rows x 64 halves (8 chunks/row), XOR swizzle
        #pragma unroll
        for (int i = 0; i < 4; i++) {
            int idx = tid + i * 256;
            int r = idx >> 3, c = idx & 7;
            cp16(Ad + r * 128 + ((c ^ (r & 7)) * 16),
                 A + (size_t)(m0 + r) * 1024 + it * 64 + c * 8);
        }
        // W tile: 64 rows x 128 halves (16 chunks/row), XOR swizzle on low 3 bits
        #pragma unroll
        for (int i = 0; i < 4; i++) {
            int idx = tid + i * 256;
            int r = idx >> 4, c = idx & 15;
            cp16(Wd + r * 256 + ((c ^ (r & 7)) * 16),
                 W + (size_t)(it * 64 + r) * N + n0 + c * 8);
        }
        cp_commit();
    };

    float acc[2][8][4] = {};
    loadTile(0, 0);
    loadTile(1, 1);

    for (int it = 0; it < 16; it++) {
        if (it < 15) cp_wait<1>(); else cp_wait<0>();
        __syncthreads();

        const char* Ab = Ast(it % 3);
        const char* Wb = Wst(it % 3);
        #pragma unroll
        for (int ks = 0; ks < 4; ks++) {
            uint32_t afr[2][4];
            #pragma unroll
            for (int mt = 0; mt < 2; mt++) {
                int row = wm * 32 + mt * 16 + ((lane >> 3) & 1) * 8 + (lane & 7);
                int ch  = (ks * 16 + (lane >> 4) * 8) >> 3;
                ldsm_x4(smem_u32(Ab + row * 128 + ((ch ^ (row & 7)) * 16)),
                        afr[mt][0], afr[mt][1], afr[mt][2], afr[mt][3]);
            }
            #pragma unroll
            for (int np = 0; np < 4; np++) {
                int rowb = ks * 16 + (lane & 15);
                int ch   = (wn * 64 + np * 16 + (lane >> 4) * 8) >> 3;
                uint32_t b0, b1, b2, b3;
                ldsm_x4_t(smem_u32(Wb + rowb * 256 + ((ch ^ (rowb & 7)) * 16)),
                          b0, b1, b2, b3);
                #pragma unroll
                for (int mt = 0; mt < 2; mt++) {
                    mma16816h(acc[mt][np * 2 + 0], afr[mt], b0, b1);
                    mma16816h(acc[mt][np * 2 + 1], afr[mt], b2, b3);
                }
            }
        }
        if (it + 2 < 16) loadTile((it + 2) % 3, it + 2);
    }

    const int g = lane >> 2, q = lane & 3;
    #pragma unroll
    for (int mt = 0; mt < 2; mt++) {
        #pragma unroll
        for (int nt = 0; nt < 8; nt++) {
            int r = m0 + wm * 32 + mt * 16 + g;
            int c = n0 + wn * 64 + nt * 8 + q * 2;
            float b0 = __ldg(bias + c), b1 = __ldg(bias + c + 1);
            *(uint32_t*)(out + (size_t)r * N + c) =
                pack_f16((acc[mt][nt][0] + b0) * oscale, (acc[mt][nt][1] + b1) * oscale);
            *(uint32_t*)(out + (size_t)(r + 8) * N + c) =
                pack_f16((acc[mt][nt][2] + b0) * oscale, (acc[mt][nt][3] + b1) * oscale);
        }
    }
}

// ---------------- flash attention, dv-split, f16x2 softmax (R15, best passing) ----------------
// grid (qt=16, h*2+dvh=16, b=4). smem: Q[128][40] @0 | K 3x[128][40] @10240 |
// V 3x[128][88] @40960 (col 64 = ones)  -> 108,544 B, 2 CTAs/SM
__global__ void __launch_bounds__(256, 2) attn_kernel(
    const float* __restrict__ x, const float* __restrict__ gamma,
    float* __restrict__ out)
{
    extern __shared__ char smem[];
    __half (*Qs)[40] = (__half(*)[40])(smem);
    const int tid  = threadIdx.x;
    const int lane = tid & 31;
    const int warp = tid >> 5;
    const int qt = blockIdx.x, b = blockIdx.z;
    const int h = blockIdx.y >> 1, dvh = blockIdx.y & 1;

    const __half* Qg = g_Q + ((size_t)(b * Mn + qt * 128)) * 256 + h * DQK;
    const __half* Kg = g_K + ((size_t)(b * Mn)) * 256 + h * DQK;
    const __half* Vg = g_V + ((size_t)(b * Mn)) * 1024 + h * DV + dvh * 64;

    auto Kst = [&](int s) { return (__half(*)[40])(smem + 10240 + s * 10240); };
    auto Vst = [&](int s) { return (__half(*)[88])(smem + 40960 + s * 22528); };

    auto loadKV = [&](int s, int kt) {
        __half (*Ks)[40] = Kst(s);
        __half (*Vs)[88] = Vst(s);
        #pragma unroll
        for (int i = 0; i < 2; i++) {
            int idx = tid + i * 256;
            int r = idx >> 2, c = idx & 3;
            cp16(&Ks[r][c * 8], Kg + (size_t)(kt * 128 + r) * 256 + c * 8);
        }
        #pragma unroll
        for (int i = 0; i < 4; i++) {
            int idx = tid + i * 256;
            int r = idx >> 3, c = idx & 7;
            cp16(&Vs[r][c * 8], Vg + (size_t)(kt * 128 + r) * 1024 + c * 8);
        }
        cp_commit();
    };

    // ones-column init (col 64 = 1, cols 65-79 = 0) for all 3 V stages
    for (int i = tid; i < 3 * 128; i += 256) {
        int s = i >> 7, r = i & 127;
        __half* vr = &Vst(s)[r][0];
        vr[64] = __float2half(1.f);
        #pragma unroll
        for (int c = 65; c < 80; c++) vr[c] = __float2half(0.f);
    }

    // Q tile [128][32]
    #pragma unroll
    for (int i = 0; i < 2; i++) {
        int idx = tid + i * 256;
        int r = idx >> 2, c = idx & 3;
        *(int4*)(&Qs[r][c * 8]) = *(const int4*)(Qg + (size_t)r * 256 + c * 8);
    }
    loadKV(0, 0);
    loadKV(1, 1);
    __syncthreads();

    uint32_t qfr[2][4];
    const int qrow0 = warp * 16;
    #pragma unroll
    for (int kc = 0; kc < 2; kc++) {
        int row = qrow0 + ((lane >> 3) & 1) * 8 + (lane & 7);
        int col = kc * 16 + (lane >> 4) * 8;
        ldsm_x4(smem_u32(&Qs[row][col]), qfr[kc][0], qfr[kc][1], qfr[kc][2], qfr[kc][3]);
    }

    float oacc[9][4];   // [0..7]: 64 dv cols; [8]: l (ones column)
    #pragma unroll
    for (int i = 0; i < 9; i++)
        #pragma unroll
        for (int j = 0; j < 4; j++) oacc[i][j] = 0.f;

    for (int kt = 0; kt < 16; kt++) {
        if (kt < 15) cp_wait<1>(); else cp_wait<0>();
        __syncthreads();
        __half (*Ks)[40] = Kst(kt % 3);
        __half (*Vs)[88] = Vst(kt % 3);

        uint32_t pfr[32];
        #pragma unroll
        for (int nt = 0; nt < 16; nt++) {
            float scv[4] = {0.f, 0.f, 0.f, 0.f};
            int rowb = nt * 8 + (lane & 7);
            int colb = (lane >> 3) * 8;
            uint32_t k0, k1, k2, k3;
            ldsm_x4(smem_u32(&Ks[rowb][colb]), k0, k1, k2, k3);
            mma16816h(scv, qfr[0], k0, k1);
            mma16816h(scv, qfr[1], k2, k3);
            pfr[2 * nt]     = exp2_pair(scv[0], scv[1]);
            pfr[2 * nt + 1] = exp2_pair(scv[2], scv[3]);
        }

        #pragma unroll
        for (int kc = 0; kc < 8; kc++) {
            uint32_t pa[4] = {pfr[4 * kc], pfr[4 * kc + 1], pfr[4 * kc + 2], pfr[4 * kc + 3]};
            int rowb = kc * 16 + (lane & 15);
            #pragma unroll
            for (int dp = 0; dp < 4; dp++) {
                int colb = dp * 16 + (lane >> 4) * 8;
                uint32_t v0, v1, v2, v3;
                ldsm_x4_t(smem_u32(&Vs[rowb][colb]), v0, v1, v2, v3);
                mma16816h(oacc[dp * 2 + 0], pa, v0, v1);
                mma16816h(oacc[dp * 2 + 1], pa, v2, v3);
            }
            {   // l column
                int colb = 64 + (lane >> 4) * 8;
                uint32_t v0, v1, v2, v3;
                ldsm_x4_t(smem_u32(&Vs[rowb][colb]), v0, v1, v2, v3);
                mma16816h(oacc[8], pa, v0, v1);
            }
        }
        if (kt + 2 < 16) loadKV((kt + 2) % 3, kt + 2);
    }

    const float l0 = __shfl_sync(0xffffffffu, oacc[8][0], lane & 28);
    const float l1 = __shfl_sync(0xffffffffu, oacc[8][2], lane & 28);

    const float gm = gamma[0];
    const float il0 = gm / l0, il1 = gm / l1;
    const int g = lane >> 2, q = lane & 3;
    const size_t row0 = (size_t)b * Mn + qt * 128 + qrow0 + g;
    const size_t row1 = row0 + 8;
    #pragma unroll
    for (int d = 0; d < 8; d++) {
        int col = h * DV + dvh * 64 + d * 8 + q * 2;
        float2 x0 = *(const float2*)(x + row0 * Cn + col);
        float2 x1 = *(const float2*)(x + row1 * Cn + col);
        float2 r0, r1;
        r0.x = oacc[d][0] * il0 + x0.x;
        r0.y = oacc[d][1] * il0 + x0.y;
        r1.x = oacc[d][2] * il1 + x1.x;
        r1.y = oacc[d][3] * il1 + x1.y;
        *(float2*)(out + row0 * Cn + col) = r0;
        *(float2*)(out + row1 * Cn + col) = r1;
    }
}

// ---------------- launch ----------------
extern "C" void kernel_launch(void* const* d_in, const int* in_sizes, int n_in,
                              void* d_out, int out_size)
{
    const float* x     = (const float*)d_in[0];
    const float* y     = (const float*)d_in[1];
    const float* Wq    = (const float*)d_in[2];
    const float* bq    = (const float*)d_in[3];
    const float* Wk    = (const float*)d_in[4];
    const float* bk    = (const float*)d_in[5];
    const float* Wv    = (const float*)d_in[6];
    const float* bv    = (const float*)d_in[7];
    const float* gamma = (const float*)d_in[8];
    float* out = (float*)d_out;

    cvt_all<<<4480, 256>>>(x, y, Wq, Wk, Wv);

    const int gemm_smem = 3 * 32768;   // 98,304 -> 2 CTAs/SM, 1 sync/iter
    cudaFuncSetAttribute(gemm_fused, cudaFuncAttributeMaxDynamicSharedMemorySize, gemm_smem);
    gemm_fused<<<768, 256, gemm_smem>>>(bq, bk, bv);

    const int attn_smem = 40960 + 3 * 22528;  // 108,544 -> 2 CTAs/SM
    cudaFuncSetAttribute(attn_kernel, cudaFuncAttributeMaxDynamicSharedMemorySize, attn_smem);
    attn_kernel<<<dim3(16, 16, 4), 256, attn_smem>>>(x, gamma, out);
}